// round 14
// baseline (speedup 1.0000x reference)
#include <cuda_runtime.h>

// ---------------------------------------------------------------------------
// Scratch (no allocation allowed -> __device__ globals)
// ---------------------------------------------------------------------------
static __device__ float g_s0[8*8*128*128];    // conv s0 out [8,8,128,128]
static __device__ float g_s1[8*16*64*64];     // [8,16,64,64]
static __device__ float g_s2[8*32*32*32];     // [8,32,32,32]
static __device__ float g_s3[8*64*16*16];     // [8,64,16,16]
static __device__ float g_l1[8*64*16*16];     // lw1 out
static __device__ float g_xl[8*64*16*16];     // lw2 out (local head)
static __device__ float g_c0[8*64*8*8];       // cw0 out
static __device__ float g_xg[8*64];           // fc3 out
static __device__ float g_bg[8*8*16*16];      // bilateral grid [B,8,16,16]
static __device__ float g_guide[8*1024*1024]; // guide map [B,1024,1024]

// grid barrier state (deterministic across replays: cnt returns to 0,
// gen compared relatively and only grows)
static __device__ unsigned g_bar_cnt = 0;
static __device__ unsigned g_bar_gen = 0;

__device__ __forceinline__ float relu_(float x){ return fmaxf(x, 0.0f); }

__device__ __forceinline__ float warp_sum(float v){
    #pragma unroll
    for (int o = 16; o > 0; o >>= 1) v += __shfl_down_sync(0xffffffffu, v, o);
    return v;
}

__device__ __forceinline__ void grid_bar() {
    __syncthreads();
    if (threadIdx.x == 0) {
        unsigned g0 = atomicAdd(&g_bar_gen, 0u);
        __threadfence();
        unsigned a = atomicAdd(&g_bar_cnt, 1u);
        if (a == gridDim.x - 1) {
            atomicExch(&g_bar_cnt, 0u);
            __threadfence();
            atomicAdd(&g_bar_gen, 1u);
        } else {
            while (atomicAdd(&g_bar_gen, 0u) == g0) __nanosleep(64);
        }
        __threadfence();
    }
    __syncthreads();
}

// Gaussian(sigma=2), 17 taps, normalized. Compile-time literals -> FFMA-imm.
static __device__ constexpr float GW[17] = {
    6.691630e-05f, 4.363500e-04f, 2.215960e-03f, 8.764310e-03f,
    2.699596e-02f, 6.475993e-02f, 1.209875e-01f, 1.760357e-01f,
    1.994747e-01f,
    1.760357e-01f, 1.209875e-01f, 6.475993e-02f, 2.699596e-02f,
    8.764310e-03f, 2.215960e-03f, 4.363500e-04f, 6.691630e-05f
};

// ---------------------------------------------------------------------------
// Generic conv3x3 phase (pad=1, stride S), block-strided over units.
// Unit = (batch, co-chunk, tile). Whole patch staged with 16-deep batching.
// Thread = (xg, cg, y), TX outputs along x, CPT co per thread. NT must be 256.
// ---------------------------------------------------------------------------
template<int CIN, int S, int COB, int CPT, int TY, int TX, int XG, bool RELU, bool HB>
__device__ void conv_phase(float* __restrict__ pool,
                           const float* __restrict__ in, const float* __restrict__ wt,
                           const float* __restrict__ bias, float* __restrict__ out,
                           int HIN, int WIN, int Cout, int HOUT, int WOUT,
                           int tilesX, int tilesY, int nUnits)
{
    constexpr int TILEW = TX*XG;
    constexpr int PH  = (TY-1)*S + 3;
    constexpr int PW  = (TILEW-1)*S + 3;
    constexpr int PWP = (PW % 2 == 0) ? PW + 1 : PW;
    constexpr int CG  = COB/CPT;
    constexpr int NT  = CG*TY*XG;
    static_assert(NT == 256, "NT must be 256");
    constexpr int WR  = (TX-1)*S + 3;
    constexpr int TOT = CIN*PH*PW;
    constexpr int WTOT = COB*CIN*9;
    constexpr int NB  = (TOT + NT*16 - 1)/(NT*16);

    float* sIn = pool;
    float* sW  = pool + CIN*PH*PWP;
    const int tid = threadIdx.x;
    const int nTiles = tilesX*tilesY;
    const int nChunks = Cout/COB;

    const int y  = tid % TY;
    const int cg = (tid / TY) % CG;
    const int xg = tid / (TY*CG);

    for (int u = blockIdx.x; u < nUnits; u += gridDim.x) {
        int tile  = u % nTiles;
        int chunk = (u / nTiles) % nChunks;
        int b     = u / (nTiles*nChunks);
        int tileX = (tile % tilesX)*TILEW;
        int tileY = (tile / tilesX)*TY;
        int co0   = chunk*COB;
        const int iy0 = tileY*S - 1, ix0 = tileX*S - 1;
        const float* inb = in + (long)b*CIN*HIN*WIN;

        __syncthreads();   // previous unit's compute reads done
        #pragma unroll 1
        for (int bb = 0; bb < NB; bb++) {
            float v[16];
            #pragma unroll
            for (int j = 0; j < 16; j++) {
                int i = (bb*16 + j)*NT + tid;
                v[j] = 0.0f;
                if (i < TOT) {
                    int ci = i / (PH*PW); int rem = i - ci*(PH*PW);
                    int r = rem / PW;     int c = rem - r*PW;
                    int iy = iy0 + r, ix = ix0 + c;
                    if ((unsigned)iy < (unsigned)HIN && (unsigned)ix < (unsigned)WIN)
                        v[j] = __ldg(&inb[(ci*HIN + iy)*WIN + ix]);
                }
            }
            #pragma unroll
            for (int j = 0; j < 16; j++) {
                int i = (bb*16 + j)*NT + tid;
                if (i < TOT) {
                    int ci = i / (PH*PW); int rem = i - ci*(PH*PW);
                    int r = rem / PW;     int c = rem - r*PW;
                    sIn[(ci*PH + r)*PWP + c] = v[j];
                }
            }
        }
        for (int i = tid; i < WTOT; i += NT)
            sW[i] = __ldg(&wt[(long)co0*CIN*9 + i]);
        __syncthreads();

        float acc[CPT][TX];
        #pragma unroll
        for (int c = 0; c < CPT; c++)
            #pragma unroll
            for (int x = 0; x < TX; x++) acc[c][x] = 0.0f;

        #pragma unroll 1
        for (int ci = 0; ci < CIN; ci++) {
            float w[CPT][9];
            #pragma unroll
            for (int c = 0; c < CPT; c++)
                #pragma unroll
                for (int k = 0; k < 9; k++)
                    w[c][k] = sW[(cg*CPT + c)*CIN*9 + ci*9 + k];
            #pragma unroll
            for (int ky = 0; ky < 3; ky++) {
                const float* rp = &sIn[(ci*PH + y*S + ky)*PWP + xg*TX*S];
                float row[WR];
                #pragma unroll
                for (int j = 0; j < WR; j++) row[j] = rp[j];
                #pragma unroll
                for (int x = 0; x < TX; x++)
                    #pragma unroll
                    for (int kx = 0; kx < 3; kx++)
                        #pragma unroll
                        for (int c = 0; c < CPT; c++)
                            acc[c][x] = fmaf(row[x*S + kx], w[c][ky*3 + kx], acc[c][x]);
            }
        }

        #pragma unroll
        for (int c = 0; c < CPT; c++) {
            int co = co0 + cg*CPT + c;
            float bv = HB ? bias[co] : 0.0f;
            #pragma unroll
            for (int x = 0; x < TX; x++) {
                float v = acc[c][x] + bv;
                if (RELU) v = relu_(v);
                out[(((long)b*Cout + co)*HOUT + tileY + y)*WOUT + tileX + xg*TX + x] = v;
            }
        }
    }
}

// ---------------------------------------------------------------------------
// s0 phase: in = concat(nearest(lqs,256), evs) -> conv3x3 s2 p1 relu
//           -> [8,8,128,128]. 512 units (64 tiles x 8 b).
// ---------------------------------------------------------------------------
__device__ void s0_phase(float* __restrict__ pool,
                         const float* __restrict__ lqs, const float* __restrict__ evs,
                         const float* __restrict__ wt,  const float* __restrict__ bias,
                         float* __restrict__ out)
{
    constexpr int PH = 33, PW = 33, PWP = 33, NT = 256;
    constexpr int TOT = 18*PH*PW;
    constexpr int NB  = (TOT + NT*16 - 1)/(NT*16);
    float* sIn = pool;
    float* sW  = pool + 18*PH*PWP;

    const int tid = threadIdx.x;
    const int y  = tid % 16;
    const int cg = (tid / 16) % 8;
    const int xg = tid / 128;

    for (int u = blockIdx.x; u < 512; u += gridDim.x) {
        int tile = u % 64, b = u / 64;
        int tileX = (tile % 8) * 16;
        int tileY = (tile / 8) * 16;
        const int iy0 = tileY*2 - 1, ix0 = tileX*2 - 1;

        __syncthreads();
        #pragma unroll 1
        for (int bb = 0; bb < NB; bb++) {
            float v[16];
            #pragma unroll
            for (int j = 0; j < 16; j++) {
                int i = (bb*16 + j)*NT + tid;
                v[j] = 0.0f;
                if (i < TOT) {
                    int ci = i / (PH*PW); int rem = i - ci*(PH*PW);
                    int r = rem / PW;     int c = rem - r*PW;
                    int iy = iy0 + r, ix = ix0 + c;
                    if ((unsigned)iy < 256u && (unsigned)ix < 256u) {
                        if (ci < 3) v[j] = __ldg(&lqs[(b*3 + ci)*1048576 + iy*4096 + ix*4]);
                        else        v[j] = __ldg(&evs[(b*15 + (ci-3))*65536 + iy*256 + ix]);
                    }
                }
            }
            #pragma unroll
            for (int j = 0; j < 16; j++) {
                int i = (bb*16 + j)*NT + tid;
                if (i < TOT) {
                    int ci = i / (PH*PW); int rem = i - ci*(PH*PW);
                    int r = rem / PW;     int c = rem - r*PW;
                    sIn[(ci*PH + r)*PWP + c] = v[j];
                }
            }
        }
        for (int i = tid; i < 8*18*9; i += NT) sW[i] = __ldg(&wt[i]);
        __syncthreads();

        float acc[8];
        #pragma unroll
        for (int x = 0; x < 8; x++) acc[x] = 0.0f;

        #pragma unroll 1
        for (int ci = 0; ci < 18; ci++) {
            float w[9];
            #pragma unroll
            for (int k = 0; k < 9; k++) w[k] = sW[(cg*18 + ci)*9 + k];
            #pragma unroll
            for (int ky = 0; ky < 3; ky++) {
                const float* rp = &sIn[(ci*PH + y*2 + ky)*PWP + xg*16];
                float row[17];
                #pragma unroll
                for (int j = 0; j < 17; j++) row[j] = rp[j];
                #pragma unroll
                for (int x = 0; x < 8; x++)
                    #pragma unroll
                    for (int kx = 0; kx < 3; kx++)
                        acc[x] = fmaf(row[x*2 + kx], w[ky*3 + kx], acc[x]);
            }
        }
        float bv = bias[cg];
        #pragma unroll
        for (int x = 0; x < 8; x++)
            out[((b*8 + cg)*128 + tileY + y)*128 + tileX + xg*8 + x] = relu_(acc[x] + bv);
    }
}

// ---------------------------------------------------------------------------
// cw1 conv + FC stack phase (8 units = batches). cw1 weights streamed via L1.
// ---------------------------------------------------------------------------
__device__ void cw1fc_phase(float* __restrict__ pool,
                            const float* __restrict__ c0,
                            const float* __restrict__ cw1, const float* __restrict__ cb1,
                            const float* __restrict__ fw1, const float* __restrict__ fb1,
                            const float* __restrict__ fw2, const float* __restrict__ fb2,
                            const float* __restrict__ fw3, const float* __restrict__ fb3,
                            float* __restrict__ xg)
{
    float* sC  = pool;           // 64*10*11 = 7040
    float* sc1 = pool + 7040;    // 1024
    float* s1f = sc1 + 1024;     // 256
    float* s2f = s1f + 256;      // 128
    const int tid = threadIdx.x;

    for (int u = blockIdx.x; u < 8; u += gridDim.x) {
        int b = u;
        __syncthreads();
        for (int i = tid; i < 64*10*10; i += 256) {
            int ci = i / 100; int rem = i - ci*100;
            int r = rem / 10, c = rem - (rem/10)*10;
            int iy = r - 1, ix = c - 1;
            float v = 0.0f;
            if ((unsigned)iy < 8u && (unsigned)ix < 8u)
                v = __ldg(&c0[((b*64 + ci)*8 + iy)*8 + ix]);
            sC[(ci*10 + r)*11 + c] = v;
        }
        __syncthreads();

        {
            int co = tid >> 2, y = tid & 3;
            float acc[4] = {0.0f, 0.0f, 0.0f, 0.0f};
            #pragma unroll 1
            for (int ci = 0; ci < 64; ci++) {
                float w[9];
                #pragma unroll
                for (int k = 0; k < 9; k++) w[k] = __ldg(&cw1[(co*64 + ci)*9 + k]);
                #pragma unroll
                for (int ky = 0; ky < 3; ky++) {
                    const float* rp = &sC[(ci*10 + y*2 + ky)*11];
                    float row[9];
                    #pragma unroll
                    for (int j = 0; j < 9; j++) row[j] = rp[j];
                    #pragma unroll
                    for (int x = 0; x < 4; x++)
                        #pragma unroll
                        for (int kx = 0; kx < 3; kx++)
                            acc[x] = fmaf(row[x*2 + kx], w[ky*3 + kx], acc[x]);
                }
            }
            float bv = cb1[co];
            #pragma unroll
            for (int x = 0; x < 4; x++)
                sc1[co*16 + y*4 + x] = relu_(acc[x] + bv);
        }
        __syncthreads();

        const int lane = tid & 31, wp = tid >> 5;

        for (int j0 = 0; j0 < 32; j0 += 4) {
            int o = wp*32 + j0;
            const float* w0 = fw1 + o*1024;
            float a0 = 0.0f, a1 = 0.0f, a2 = 0.0f, a3 = 0.0f;
            #pragma unroll 4
            for (int k = lane; k < 1024; k += 32) {
                float xv = sc1[k];
                a0 = fmaf(w0[k],        xv, a0);
                a1 = fmaf(w0[k + 1024], xv, a1);
                a2 = fmaf(w0[k + 2048], xv, a2);
                a3 = fmaf(w0[k + 3072], xv, a3);
            }
            a0 = warp_sum(a0); a1 = warp_sum(a1); a2 = warp_sum(a2); a3 = warp_sum(a3);
            if (lane == 0) {
                s1f[o]   = relu_(a0 + fb1[o]);
                s1f[o+1] = relu_(a1 + fb1[o+1]);
                s1f[o+2] = relu_(a2 + fb1[o+2]);
                s1f[o+3] = relu_(a3 + fb1[o+3]);
            }
        }
        __syncthreads();

        for (int j0 = 0; j0 < 16; j0 += 4) {
            int o = wp*16 + j0;
            const float* w0 = fw2 + o*256;
            float a0 = 0.0f, a1 = 0.0f, a2 = 0.0f, a3 = 0.0f;
            #pragma unroll
            for (int k = lane; k < 256; k += 32) {
                float xv = s1f[k];
                a0 = fmaf(w0[k],       xv, a0);
                a1 = fmaf(w0[k + 256], xv, a1);
                a2 = fmaf(w0[k + 512], xv, a2);
                a3 = fmaf(w0[k + 768], xv, a3);
            }
            a0 = warp_sum(a0); a1 = warp_sum(a1); a2 = warp_sum(a2); a3 = warp_sum(a3);
            if (lane == 0) {
                s2f[o]   = relu_(a0 + fb2[o]);
                s2f[o+1] = relu_(a1 + fb2[o+1]);
                s2f[o+2] = relu_(a2 + fb2[o+2]);
                s2f[o+3] = relu_(a3 + fb2[o+3]);
            }
        }
        __syncthreads();

        for (int j0 = 0; j0 < 8; j0 += 4) {
            int o = wp*8 + j0;
            const float* w0 = fw3 + o*128;
            float a0 = 0.0f, a1 = 0.0f, a2 = 0.0f, a3 = 0.0f;
            #pragma unroll
            for (int k = lane; k < 128; k += 32) {
                float xv = s2f[k];
                a0 = fmaf(w0[k],       xv, a0);
                a1 = fmaf(w0[k + 128], xv, a1);
                a2 = fmaf(w0[k + 256], xv, a2);
                a3 = fmaf(w0[k + 384], xv, a3);
            }
            a0 = warp_sum(a0); a1 = warp_sum(a1); a2 = warp_sum(a2); a3 = warp_sum(a3);
            if (lane == 0) {
                xg[b*64 + o]   = a0 + fb3[o];
                xg[b*64 + o+1] = a1 + fb3[o+1];
                xg[b*64 + o+2] = a2 + fb3[o+2];
                xg[b*64 + o+3] = a3 + fb3[o+3];
            }
        }
    }
}

// ---------------------------------------------------------------------------
// bg phase: conv1x1(relu(xg + xl)) -> [B,8,16,16]. 8 units.
// ---------------------------------------------------------------------------
__device__ void bg_phase(float* __restrict__ pool,
                         const float* __restrict__ xl, const float* __restrict__ xg,
                         const float* __restrict__ fuw, const float* __restrict__ fub,
                         float* __restrict__ bg)
{
    float* sxg = pool;        // 64
    float* sw  = pool + 64;   // 512
    const int p = threadIdx.x;

    for (int u = blockIdx.x; u < 8; u += gridDim.x) {
        int b = u;
        __syncthreads();
        if (p < 64) sxg[p] = xg[b*64 + p];
        for (int i = p; i < 512; i += 256) sw[i] = fuw[i];
        __syncthreads();
        float acc[8];
        #pragma unroll
        for (int g = 0; g < 8; g++) acc[g] = fub[g];
        for (int c = 0; c < 64; c++) {
            float f = relu_(sxg[c] + xl[(b*64 + c)*256 + p]);
            #pragma unroll
            for (int g = 0; g < 8; g++) acc[g] = fmaf(sw[g*64 + c], f, acc[g]);
        }
        #pragma unroll
        for (int g = 0; g < 8; g++) bg[(b*8 + g)*256 + p] = acc[g];
    }
}

// ---------------------------------------------------------------------------
// trunk_kernel: entire lowres path in one persistent kernel w/ grid barriers.
// ---------------------------------------------------------------------------
__global__ __launch_bounds__(256)
void trunk_kernel(const float* __restrict__ lqs, const float* __restrict__ evs,
                  const float* __restrict__ sw0, const float* __restrict__ sb0,
                  const float* __restrict__ sw1, const float* __restrict__ sb1,
                  const float* __restrict__ sw2, const float* __restrict__ sb2,
                  const float* __restrict__ sw3, const float* __restrict__ sb3,
                  const float* __restrict__ lw1, const float* __restrict__ lb1,
                  const float* __restrict__ lw2,
                  const float* __restrict__ cw0, const float* __restrict__ cb0,
                  const float* __restrict__ cw1, const float* __restrict__ cb1,
                  const float* __restrict__ fw1, const float* __restrict__ fb1,
                  const float* __restrict__ fw2, const float* __restrict__ fb2,
                  const float* __restrict__ fw3, const float* __restrict__ fb3,
                  const float* __restrict__ fuw, const float* __restrict__ fub)
{
    extern __shared__ float pool[];

    // P0: s0 (512 units)
    s0_phase(pool, lqs, evs, sw0, sb0, g_s0);
    grid_bar();
    // P1: s1  in[8,128,128] -> out[16,64,64], 128 units
    conv_phase<8,2,16,2,16,8,2,true,true>(pool, g_s0, sw1, sb1, g_s1,
                                          128, 128, 16, 64, 64, 4, 4, 128);
    grid_bar();
    // P2: s2  in[16,64,64] -> out[32,32,32], 128 units
    conv_phase<16,2,8,1,16,8,2,true,true>(pool, g_s1, sw2, sb2, g_s2,
                                          64, 64, 32, 32, 32, 2, 2, 128);
    grid_bar();
    // P3: s3  in[32,32,32] -> out[64,16,16], 128 units
    conv_phase<32,2,8,1,8,4,4,true,true>(pool, g_s2, sw3, sb3, g_s3,
                                         32, 32, 64, 16, 16, 1, 2, 128);
    grid_bar();
    // P4: lw1 in[64,16,16] -> out[64,16,16], 128 units
    conv_phase<64,1,8,1,16,4,2,true,true>(pool, g_s3, lw1, lb1, g_l1,
                                          16, 16, 64, 16, 16, 2, 1, 128);
    grid_bar();
    // P5: lw2 (no relu/bias), then P6: cw0 (independent; same barrier window)
    conv_phase<64,1,8,1,16,4,2,false,false>(pool, g_l1, lw2, (const float*)nullptr, g_xl,
                                            16, 16, 64, 16, 16, 2, 1, 128);
    conv_phase<64,2,8,1,8,2,4,true,true>(pool, g_s3, cw0, cb0, g_c0,
                                         16, 16, 64, 8, 8, 1, 1, 64);
    grid_bar();
    // P7: cw1 conv + FC stack (8 units)
    cw1fc_phase(pool, g_c0, cw1, cb1, fw1, fb1, fw2, fb2, fw3, fb3, g_xg);
    grid_bar();
    // P8: bilateral grid (8 units)
    bg_phase(pool, g_xl, g_xg, fuw, fub, g_bg);
}

// ---------------------------------------------------------------------------
// guide_kernel: Gaussian blur (separable, reflect) + 1x1 convs -> guide map.
// ---------------------------------------------------------------------------
__device__ __forceinline__ int reflect1024(int i) {
    return i < 0 ? -i : (i > 1023 ? 2046 - i : i);
}

__global__ __launch_bounds__(256, 2)
void guide_kernel(const float* __restrict__ lqs,
                  const float* __restrict__ gw1, const float* __restrict__ gb1,
                  const float* __restrict__ gw2, const float* __restrict__ gb2,
                  float* __restrict__ guide)
{
    __shared__ float sIn[3][48][49];
    __shared__ float sMid[3][48][33];
    __shared__ float sW[81];

    const int tid = threadIdx.x;
    const int bx = blockIdx.x*32, by = blockIdx.y*32, b = blockIdx.z;

    if (tid < 81)
        sW[tid] = (tid < 48) ? gw1[tid]
                : (tid < 64) ? gb1[tid - 48]
                : (tid < 80) ? gw2[tid - 64] : gb2[0];

    const float* base = lqs + b*3*1048576;

    for (int i = tid; i < 3*48*48; i += 256) {
        int ch = i / 2304; int rem = i - ch*2304;
        int r = rem / 48;  int c  = rem - r*48;
        sIn[ch][r][c] = base[ch*1048576 + reflect1024(by + r - 8)*1024 + reflect1024(bx + c - 8)];
    }
    __syncthreads();

    for (int s = tid; s < 288; s += 256) {
        int ch = s / 96; int rem = s - ch*96;
        int r = rem >> 1; int half = rem & 1;
        int c0 = half * 16;
        float w[32];
        #pragma unroll
        for (int j = 0; j < 32; j++) w[j] = sIn[ch][r][c0 + j];
        #pragma unroll
        for (int o = 0; o < 16; o++) {
            float a = 0.0f;
            #pragma unroll
            for (int k = 0; k < 17; k++) a = fmaf(GW[k], w[o + k], a);
            sMid[ch][r][c0 + o] = a;
        }
    }
    __syncthreads();

    const int tx = tid & 31;
    const int qy = tid >> 5;
    float vb[3][4];
    #pragma unroll
    for (int ch = 0; ch < 3; ch++) {
        float col[20];
        #pragma unroll
        for (int k = 0; k < 20; k++) col[k] = sMid[ch][qy*4 + k][tx];
        #pragma unroll
        for (int d = 0; d < 4; d++) {
            float a = 0.0f;
            #pragma unroll
            for (int k = 0; k < 17; k++) a = fmaf(GW[k], col[d + k], a);
            vb[ch][d] = a;
        }
    }

    const int ox = bx + tx;
    #pragma unroll
    for (int d = 0; d < 4; d++) {
        float ssum = sW[80];
        #pragma unroll
        for (int o = 0; o < 16; o++) {
            float h = fmaf(sW[o*3], vb[0][d], fmaf(sW[o*3+1], vb[1][d], fmaf(sW[o*3+2], vb[2][d], sW[48+o])));
            h = relu_(h);
            ssum = fmaf(sW[64+o], h, ssum);
        }
        float sig = 1.0f / (1.0f + __expf(-ssum));
        int oy = by + qy*4 + d;
        guide[b*1048576 + oy*1024 + ox] = 2.0f*sig - 0.5f;
    }
}

// ---------------------------------------------------------------------------
// slice_kernel: trilinear slice of bilateral grid using guide map. float4 I/O.
// ---------------------------------------------------------------------------
__global__ void slice_kernel(const float* __restrict__ guide,
                             const float* __restrict__ bg, float* __restrict__ out)
{
    int idx = blockIdx.x*256 + threadIdx.x;     // 2,097,152 threads (x4 px)
    int b   = idx >> 18;
    int rem = idx & 0x3FFFF;
    int py  = rem >> 8;
    int px0 = (rem & 255) << 2;

    float4 g4 = ((const float4*)guide)[idx];
    float gv[4] = {g4.x, g4.y, g4.z, g4.w};

    float gyv = (py + 0.5f) * (1.0f/1024.0f) * 2.0f - 0.5f;
    float ys  = fminf(fmaxf(((gyv + 1.0f)*16.0f - 1.0f)*0.5f, 0.0f), 15.0f);
    float y0f = floorf(ys);
    int   y0  = (int)y0f;
    float fy  = ys - y0f;
    int   y1  = min(y0 + 1, 15);

    const float* bgb = bg + b*2048;
    float res[4];
    #pragma unroll
    for (int j = 0; j < 4; j++) {
        int px = px0 + j;
        float gxv = (px + 0.5f) * (1.0f/1024.0f) * 2.0f - 0.5f;
        float xs  = fminf(fmaxf(((gxv + 1.0f)*16.0f - 1.0f)*0.5f, 0.0f), 15.0f);
        float x0f = floorf(xs);
        int   x0  = (int)x0f;
        float fx  = xs - x0f;
        int   x1  = min(x0 + 1, 15);

        float zs  = fminf(fmaxf(((gv[j] + 1.0f)*8.0f - 1.0f)*0.5f, 0.0f), 7.0f);
        float z0f = floorf(zs);
        int   z0  = (int)z0f;
        float fz  = zs - z0f;
        int   z1  = min(z0 + 1, 7);

        float v000 = __ldg(&bgb[z0*256 + y0*16 + x0]);
        float v001 = __ldg(&bgb[z0*256 + y0*16 + x1]);
        float v010 = __ldg(&bgb[z0*256 + y1*16 + x0]);
        float v011 = __ldg(&bgb[z0*256 + y1*16 + x1]);
        float v100 = __ldg(&bgb[z1*256 + y0*16 + x0]);
        float v101 = __ldg(&bgb[z1*256 + y0*16 + x1]);
        float v110 = __ldg(&bgb[z1*256 + y1*16 + x0]);
        float v111 = __ldg(&bgb[z1*256 + y1*16 + x1]);

        float c00 = v000 + (v001 - v000)*fx;
        float c01 = v010 + (v011 - v010)*fx;
        float c10 = v100 + (v101 - v100)*fx;
        float c11 = v110 + (v111 - v110)*fx;
        float c0v = c00 + (c01 - c00)*fy;
        float c1v = c10 + (c11 - c10)*fy;
        res[j] = c0v + (c1v - c0v)*fz;
    }
    ((float4*)out)[idx] = make_float4(res[0], res[1], res[2], res[3]);
}

// ---------------------------------------------------------------------------
// kernel_launch
// ---------------------------------------------------------------------------
extern "C" void kernel_launch(void* const* d_in, const int* in_sizes, int n_in,
                              void* d_out, int out_size)
{
    const float* lqs = (const float*)d_in[0];
    const float* evs = (const float*)d_in[1];
    const float* gw1 = (const float*)d_in[2];
    const float* gb1 = (const float*)d_in[3];
    const float* gw2 = (const float*)d_in[4];
    const float* gb2 = (const float*)d_in[5];
    const float* sw0 = (const float*)d_in[6];
    const float* sb0 = (const float*)d_in[7];
    const float* sw1 = (const float*)d_in[8];
    const float* sb1 = (const float*)d_in[9];
    const float* sw2 = (const float*)d_in[10];
    const float* sb2 = (const float*)d_in[11];
    const float* sw3 = (const float*)d_in[12];
    const float* sb3 = (const float*)d_in[13];
    const float* cw0 = (const float*)d_in[14];
    const float* cb0 = (const float*)d_in[15];
    const float* cw1 = (const float*)d_in[16];
    const float* cb1 = (const float*)d_in[17];
    const float* fw1 = (const float*)d_in[18];
    const float* fb1 = (const float*)d_in[19];
    const float* fw2 = (const float*)d_in[20];
    const float* fb2 = (const float*)d_in[21];
    const float* fw3 = (const float*)d_in[22];
    const float* fb3 = (const float*)d_in[23];
    const float* lw1 = (const float*)d_in[24];
    const float* lb1 = (const float*)d_in[25];
    const float* lw2 = (const float*)d_in[26];
    const float* fuw = (const float*)d_in[27];
    const float* fub = (const float*)d_in[28];
    float* out = (float*)d_out;

    float *pbg, *pgd;
    cudaGetSymbolAddress((void**)&pbg, g_bg);
    cudaGetSymbolAddress((void**)&pgd, g_guide);

    const int POOL = 23104 * 4;   // 92416 B: max over phases (cw0: 64*17*17 + 8*64*9)

    static cudaStream_t s_side = nullptr;
    static cudaEvent_t  ev_fork = nullptr, ev_join = nullptr;
    if (!s_side) {
        cudaStreamCreateWithFlags(&s_side, cudaStreamNonBlocking);
        cudaEventCreateWithFlags(&ev_fork, cudaEventDisableTiming);
        cudaEventCreateWithFlags(&ev_join, cudaEventDisableTiming);
        cudaFuncSetAttribute(trunk_kernel, cudaFuncAttributeMaxDynamicSharedMemorySize, POOL);
    }

    // ---- fork: guide path runs concurrent with the lowres trunk ----
    cudaEventRecord(ev_fork, 0);
    cudaStreamWaitEvent(s_side, ev_fork, 0);
    guide_kernel<<<dim3(32, 32, 8), 256, 0, s_side>>>(lqs, gw1, gb1, gw2, gb2, pgd);

    // ---- entire lowres path: ONE persistent kernel with grid barriers ----
    trunk_kernel<<<128, 256, POOL>>>(lqs, evs, sw0, sb0, sw1, sb1, sw2, sb2, sw3, sb3,
                                     lw1, lb1, lw2, cw0, cb0, cw1, cb1,
                                     fw1, fb1, fw2, fb2, fw3, fb3, fuw, fub);

    // ---- join guide, slice ----
    cudaEventRecord(ev_join, s_side);
    cudaStreamWaitEvent(0, ev_join, 0);
    slice_kernel<<<8192, 256>>>(pgd, pbg, out);
}

// round 15
// speedup vs baseline: 1.3875x; 1.3875x over previous
#include <cuda_runtime.h>

// ---------------------------------------------------------------------------
// Scratch (no allocation allowed -> __device__ globals)
// ---------------------------------------------------------------------------
static __device__ float g_s0[8*8*128*128];    // conv s0 out [8,8,128,128]
static __device__ float g_s1[8*16*64*64];     // [8,16,64,64]
static __device__ float g_s2[8*32*32*32];     // [8,32,32,32]
static __device__ float g_s3[8*64*16*16];     // [8,64,16,16]
static __device__ float g_l1[8*64*16*16];     // lw1 out
static __device__ float g_xl[8*64*16*16];     // lw2 out (local head)
static __device__ float g_c0[8*64*8*8];       // cw0 out
static __device__ float g_xg[8*64];           // fc3 out
static __device__ float g_bg[8*8*16*16];      // bilateral grid [B,8,16,16]
static __device__ float g_mid[8*3*1024*1024]; // h-blurred lqs [B,3,1024,1024]

__device__ __forceinline__ float relu_(float x){ return fmaxf(x, 0.0f); }

__device__ __forceinline__ float warp_sum(float v){
    #pragma unroll
    for (int o = 16; o > 0; o >>= 1) v += __shfl_down_sync(0xffffffffu, v, o);
    return v;
}

// Gaussian(sigma=2), 17 taps, normalized. Compile-time literals -> FFMA-imm.
static __device__ constexpr float GW[17] = {
    6.691630e-05f, 4.363500e-04f, 2.215960e-03f, 8.764310e-03f,
    2.699596e-02f, 6.475993e-02f, 1.209875e-01f, 1.760357e-01f,
    1.994747e-01f,
    1.760357e-01f, 1.209875e-01f, 6.475993e-02f, 2.699596e-02f,
    8.764310e-03f, 2.215960e-03f, 4.363500e-04f, 6.691630e-05f
};

__device__ __forceinline__ int reflect1024(int i) {
    return i < 0 ? -i : (i > 1023 ? 2046 - i : i);
}

// ---------------------------------------------------------------------------
// convf3: 3x3 conv (pad=1, stride S). Whole input staged once per block with
// register-batched loads (8 LDG in flight -> 8 STS), 256 threads, one sync.
// ---------------------------------------------------------------------------
template<int CIN, int S, int COB, int CPT, int TY, int TX, int XG, bool RELU, bool HB>
__global__ void convf3_kernel(const float* __restrict__ in, const float* __restrict__ wt,
                              const float* __restrict__ bias, float* __restrict__ out,
                              int HIN, int WIN, int Cout, int HOUT, int WOUT, int tilesX)
{
    constexpr int TILEW = TX*XG;
    constexpr int PH  = (TY-1)*S + 3;
    constexpr int PW  = (TILEW-1)*S + 3;
    constexpr int PWP = (PW % 2 == 0) ? PW + 1 : PW;
    constexpr int CG  = COB/CPT;
    constexpr int NT  = CG*TY*XG;
    constexpr int WR  = (TX-1)*S + 3;
    constexpr int TOT = CIN*PH*PW;
    constexpr int WTOT = COB*CIN*9;
    constexpr int NB  = (TOT + NT*8 - 1)/(NT*8);

    extern __shared__ float sm[];
    float* sIn = sm;
    float* sW  = sm + CIN*PH*PWP;

    const int b     = blockIdx.z;
    const int co0   = blockIdx.y * COB;
    const int tileX = (blockIdx.x % tilesX) * TILEW;
    const int tileY = (blockIdx.x / tilesX) * TY;
    const int tid   = threadIdx.x;

    const int iy0 = tileY*S - 1, ix0 = tileX*S - 1;
    const float* inb = in + (long)b*CIN*HIN*WIN;

    #pragma unroll 1
    for (int bb = 0; bb < NB; bb++) {
        float v[8];
        #pragma unroll
        for (int j = 0; j < 8; j++) {
            int i = (bb*8 + j)*NT + tid;
            v[j] = 0.0f;
            if (i < TOT) {
                int ci = i / (PH*PW); int rem = i - ci*(PH*PW);
                int r = rem / PW;     int c = rem - r*PW;
                int iy = iy0 + r, ix = ix0 + c;
                if ((unsigned)iy < (unsigned)HIN && (unsigned)ix < (unsigned)WIN)
                    v[j] = __ldg(&inb[(ci*HIN + iy)*WIN + ix]);
            }
        }
        #pragma unroll
        for (int j = 0; j < 8; j++) {
            int i = (bb*8 + j)*NT + tid;
            if (i < TOT) {
                int ci = i / (PH*PW); int rem = i - ci*(PH*PW);
                int r = rem / PW;     int c = rem - r*PW;
                sIn[(ci*PH + r)*PWP + c] = v[j];
            }
        }
    }
    for (int i = tid; i < WTOT; i += NT)
        sW[i] = __ldg(&wt[(long)co0*CIN*9 + i]);
    __syncthreads();

    const int y  = tid % TY;
    const int cg = (tid / TY) % CG;
    const int xg = tid / (TY*CG);

    float acc[CPT][TX];
    #pragma unroll
    for (int c = 0; c < CPT; c++)
        #pragma unroll
        for (int x = 0; x < TX; x++) acc[c][x] = 0.0f;

    #pragma unroll 1
    for (int ci = 0; ci < CIN; ci++) {
        float w[CPT][9];
        #pragma unroll
        for (int c = 0; c < CPT; c++)
            #pragma unroll
            for (int k = 0; k < 9; k++)
                w[c][k] = sW[(cg*CPT + c)*CIN*9 + ci*9 + k];
        #pragma unroll
        for (int ky = 0; ky < 3; ky++) {
            const float* rp = &sIn[(ci*PH + y*S + ky)*PWP + xg*TX*S];
            float row[WR];
            #pragma unroll
            for (int j = 0; j < WR; j++) row[j] = rp[j];
            #pragma unroll
            for (int x = 0; x < TX; x++)
                #pragma unroll
                for (int kx = 0; kx < 3; kx++)
                    #pragma unroll
                    for (int c = 0; c < CPT; c++)
                        acc[c][x] = fmaf(row[x*S + kx], w[c][ky*3 + kx], acc[c][x]);
        }
    }

    #pragma unroll
    for (int c = 0; c < CPT; c++) {
        int co = co0 + cg*CPT + c;
        float bv = HB ? bias[co] : 0.0f;
        #pragma unroll
        for (int x = 0; x < TX; x++) {
            float v = acc[c][x] + bv;
            if (RELU) v = relu_(v);
            out[((b*Cout + co)*HOUT + tileY + y)*WOUT + tileX + xg*TX + x] = v;
        }
    }
}

// ---------------------------------------------------------------------------
// s0: in = concat(nearest(lqs,256), evs) [8,18,256,256] -> conv3x3 s2 p1 relu
//     -> [8,8,128,128]. Batched gathered staging, 256 thr, 512 blocks.
// ---------------------------------------------------------------------------
__global__ void s0f_kernel(const float* __restrict__ lqs, const float* __restrict__ evs,
                           const float* __restrict__ wt,  const float* __restrict__ bias,
                           float* __restrict__ out)
{
    constexpr int PH = 33, PW = 33, PWP = 33, NT = 256;
    constexpr int TOT = 18*PH*PW;
    constexpr int NB  = (TOT + NT*16 - 1)/(NT*16);
    extern __shared__ float sm[];
    float* sIn = sm;
    float* sW  = sm + 18*PH*PWP;

    const int b     = blockIdx.z;
    const int tileX = (blockIdx.x % 8) * 16;
    const int tileY = (blockIdx.x / 8) * 16;
    const int tid   = threadIdx.x;

    const int iy0 = tileY*2 - 1, ix0 = tileX*2 - 1;

    #pragma unroll 1
    for (int bb = 0; bb < NB; bb++) {
        float v[16];
        #pragma unroll
        for (int j = 0; j < 16; j++) {
            int i = (bb*16 + j)*NT + tid;
            v[j] = 0.0f;
            if (i < TOT) {
                int ci = i / (PH*PW); int rem = i - ci*(PH*PW);
                int r = rem / PW;     int c = rem - r*PW;
                int iy = iy0 + r, ix = ix0 + c;
                if ((unsigned)iy < 256u && (unsigned)ix < 256u) {
                    if (ci < 3) v[j] = __ldg(&lqs[(b*3 + ci)*1048576 + iy*4096 + ix*4]);
                    else        v[j] = __ldg(&evs[(b*15 + (ci-3))*65536 + iy*256 + ix]);
                }
            }
        }
        #pragma unroll
        for (int j = 0; j < 16; j++) {
            int i = (bb*16 + j)*NT + tid;
            if (i < TOT) {
                int ci = i / (PH*PW); int rem = i - ci*(PH*PW);
                int r = rem / PW;     int c = rem - r*PW;
                sIn[(ci*PH + r)*PWP + c] = v[j];
            }
        }
    }
    for (int i = tid; i < 8*18*9; i += NT) sW[i] = __ldg(&wt[i]);
    __syncthreads();

    const int y  = tid % 16;
    const int cg = (tid / 16) % 8;
    const int xg = tid / 128;

    float acc[8];
    #pragma unroll
    for (int x = 0; x < 8; x++) acc[x] = 0.0f;

    #pragma unroll 1
    for (int ci = 0; ci < 18; ci++) {
        float w[9];
        #pragma unroll
        for (int k = 0; k < 9; k++) w[k] = sW[(cg*18 + ci)*9 + k];
        #pragma unroll
        for (int ky = 0; ky < 3; ky++) {
            const float* rp = &sIn[(ci*PH + y*2 + ky)*PWP + xg*16];
            float row[17];
            #pragma unroll
            for (int j = 0; j < 17; j++) row[j] = rp[j];
            #pragma unroll
            for (int x = 0; x < 8; x++)
                #pragma unroll
                for (int kx = 0; kx < 3; kx++)
                    acc[x] = fmaf(row[x*2 + kx], w[ky*3 + kx], acc[x]);
        }
    }

    float bv = bias[cg];
    #pragma unroll
    for (int x = 0; x < 8; x++)
        out[((b*8 + cg)*128 + tileY + y)*128 + tileX + xg*8 + x] = relu_(acc[x] + bv);
}

// ---------------------------------------------------------------------------
// Fused cw1 (conv3x3 s2: [64,8,8]->[64,4,4]) + FC 1024->256->128->64.
// ---------------------------------------------------------------------------
__global__ void cw1fc_kernel(const float* __restrict__ c0,
                             const float* __restrict__ cw1, const float* __restrict__ cb1,
                             const float* __restrict__ fw1, const float* __restrict__ fb1,
                             const float* __restrict__ fw2, const float* __restrict__ fb2,
                             const float* __restrict__ fw3, const float* __restrict__ fb3,
                             float* __restrict__ xg)
{
    extern __shared__ float sm[];
    float* sC  = sm;             // 64*10*11 = 7040
    float* sWt = sC + 7040;      // 36864
    float* sc1 = sWt + 36864;    // 1024
    float* s1f = sc1 + 1024;     // 256
    float* s2f = s1f + 256;      // 128

    const int b = blockIdx.x, tid = threadIdx.x;

    for (int i = tid; i < 64*10*10; i += 256) {
        int ci = i / 100; int rem = i - ci*100;
        int r = rem / 10, c = rem - (rem/10)*10;
        int iy = r - 1, ix = c - 1;
        float v = 0.0f;
        if ((unsigned)iy < 8u && (unsigned)ix < 8u)
            v = c0[((b*64 + ci)*8 + iy)*8 + ix];
        sC[(ci*10 + r)*11 + c] = v;
    }
    for (int i = tid; i < 36864; i += 256) sWt[i] = cw1[i];
    __syncthreads();

    {
        int co = tid >> 2, y = tid & 3;
        float acc[4] = {0.0f, 0.0f, 0.0f, 0.0f};
        #pragma unroll 1
        for (int ci = 0; ci < 64; ci++) {
            float w[9];
            #pragma unroll
            for (int k = 0; k < 9; k++) w[k] = sWt[(co*64 + ci)*9 + k];
            #pragma unroll
            for (int ky = 0; ky < 3; ky++) {
                const float* rp = &sC[(ci*10 + y*2 + ky)*11];
                float row[9];
                #pragma unroll
                for (int j = 0; j < 9; j++) row[j] = rp[j];
                #pragma unroll
                for (int x = 0; x < 4; x++)
                    #pragma unroll
                    for (int kx = 0; kx < 3; kx++)
                        acc[x] = fmaf(row[x*2 + kx], w[ky*3 + kx], acc[x]);
            }
        }
        float bv = cb1[co];
        #pragma unroll
        for (int x = 0; x < 4; x++)
            sc1[co*16 + y*4 + x] = relu_(acc[x] + bv);
    }
    __syncthreads();

    const int lane = tid & 31, wp = tid >> 5;

    for (int j0 = 0; j0 < 32; j0 += 4) {
        int o = wp*32 + j0;
        const float* w0 = fw1 + o*1024;
        float a0 = 0.0f, a1 = 0.0f, a2 = 0.0f, a3 = 0.0f;
        #pragma unroll 4
        for (int k = lane; k < 1024; k += 32) {
            float xv = sc1[k];
            a0 = fmaf(w0[k],        xv, a0);
            a1 = fmaf(w0[k + 1024], xv, a1);
            a2 = fmaf(w0[k + 2048], xv, a2);
            a3 = fmaf(w0[k + 3072], xv, a3);
        }
        a0 = warp_sum(a0); a1 = warp_sum(a1); a2 = warp_sum(a2); a3 = warp_sum(a3);
        if (lane == 0) {
            s1f[o]   = relu_(a0 + fb1[o]);
            s1f[o+1] = relu_(a1 + fb1[o+1]);
            s1f[o+2] = relu_(a2 + fb1[o+2]);
            s1f[o+3] = relu_(a3 + fb1[o+3]);
        }
    }
    __syncthreads();

    for (int j0 = 0; j0 < 16; j0 += 4) {
        int o = wp*16 + j0;
        const float* w0 = fw2 + o*256;
        float a0 = 0.0f, a1 = 0.0f, a2 = 0.0f, a3 = 0.0f;
        #pragma unroll
        for (int k = lane; k < 256; k += 32) {
            float xv = s1f[k];
            a0 = fmaf(w0[k],       xv, a0);
            a1 = fmaf(w0[k + 256], xv, a1);
            a2 = fmaf(w0[k + 512], xv, a2);
            a3 = fmaf(w0[k + 768], xv, a3);
        }
        a0 = warp_sum(a0); a1 = warp_sum(a1); a2 = warp_sum(a2); a3 = warp_sum(a3);
        if (lane == 0) {
            s2f[o]   = relu_(a0 + fb2[o]);
            s2f[o+1] = relu_(a1 + fb2[o+1]);
            s2f[o+2] = relu_(a2 + fb2[o+2]);
            s2f[o+3] = relu_(a3 + fb2[o+3]);
        }
    }
    __syncthreads();

    for (int j0 = 0; j0 < 8; j0 += 4) {
        int o = wp*8 + j0;
        const float* w0 = fw3 + o*128;
        float a0 = 0.0f, a1 = 0.0f, a2 = 0.0f, a3 = 0.0f;
        #pragma unroll
        for (int k = lane; k < 128; k += 32) {
            float xv = s2f[k];
            a0 = fmaf(w0[k],       xv, a0);
            a1 = fmaf(w0[k + 128], xv, a1);
            a2 = fmaf(w0[k + 256], xv, a2);
            a3 = fmaf(w0[k + 384], xv, a3);
        }
        a0 = warp_sum(a0); a1 = warp_sum(a1); a2 = warp_sum(a2); a3 = warp_sum(a3);
        if (lane == 0) {
            xg[b*64 + o]   = a0 + fb3[o];
            xg[b*64 + o+1] = a1 + fb3[o+1];
            xg[b*64 + o+2] = a2 + fb3[o+2];
            xg[b*64 + o+3] = a3 + fb3[o+3];
        }
    }
}

// ---------------------------------------------------------------------------
// bg = conv1x1(relu(xg[b,c] + xl[b,c,y,x]), fuw) + fub  -> [B,8,16,16]
// ---------------------------------------------------------------------------
__global__ void bg_kernel(const float* __restrict__ xl, const float* __restrict__ xg,
                          const float* __restrict__ fuw, const float* __restrict__ fub,
                          float* __restrict__ bg)
{
    int b = blockIdx.x, p = threadIdx.x;
    __shared__ float sxg[64];
    __shared__ float sw[8*64];
    if (p < 64) sxg[p] = xg[b*64 + p];
    for (int i = p; i < 512; i += 256) sw[i] = fuw[i];
    __syncthreads();
    float acc[8];
    #pragma unroll
    for (int g = 0; g < 8; g++) acc[g] = fub[g];
    for (int c = 0; c < 64; c++) {
        float f = relu_(sxg[c] + xl[(b*64 + c)*256 + p]);
        #pragma unroll
        for (int g = 0; g < 8; g++) acc[g] = fmaf(sw[g*64 + c], f, acc[g]);
    }
    #pragma unroll
    for (int g = 0; g < 8; g++) bg[(b*8 + g)*256 + p] = acc[g];
}

// ---------------------------------------------------------------------------
// hblur_kernel: horizontal 17-tap Gaussian, reflect pad, global->global.
// Thread = 16 consecutive outputs; 12 float4 LDG -> 48-reg window -> FFMA-imm.
// grid (256, 3, 8): blockIdx.x = 4-row group; block 256 = 4 rows x 64 segs.
// ---------------------------------------------------------------------------
__global__ __launch_bounds__(256)
void hblur_kernel(const float* __restrict__ lqs, float* __restrict__ mid)
{
    const int tid = threadIdx.x;
    const int t = tid & 63;          // x segment (16 px each)
    const int r = tid >> 6;          // row within 4-row group
    const int ch = blockIdx.y, b = blockIdx.z;
    const int y = blockIdx.x*4 + r;
    const float* row  = lqs + ((b*3 + ch)*1024 + y)*1024;
    float*       orow = mid + ((b*3 + ch)*1024 + y)*1024;
    const int x0 = t*16;

    float w[48];
    if (t == 0 || t == 63) {
        #pragma unroll
        for (int j = 0; j < 48; j++) w[j] = __ldg(&row[reflect1024(x0 - 8 + j)]);
    } else {
        const float4* p = (const float4*)(row + x0 - 8);
        #pragma unroll
        for (int j = 0; j < 12; j++) {
            float4 v = __ldg(&p[j]);
            w[j*4] = v.x; w[j*4+1] = v.y; w[j*4+2] = v.z; w[j*4+3] = v.w;
        }
    }

    #pragma unroll
    for (int o = 0; o < 16; o += 4) {
        float a0 = 0.0f, a1 = 0.0f, a2 = 0.0f, a3 = 0.0f;
        #pragma unroll
        for (int k = 0; k < 17; k++) {
            a0 = fmaf(GW[k], w[o + k],     a0);
            a1 = fmaf(GW[k], w[o + 1 + k], a1);
            a2 = fmaf(GW[k], w[o + 2 + k], a2);
            a3 = fmaf(GW[k], w[o + 3 + k], a3);
        }
        *(float4*)(orow + x0 + o) = make_float4(a0, a1, a2, a3);
    }
}

// ---------------------------------------------------------------------------
// vslice_kernel: vertical blur + 1x1 head + sigmoid + trilinear slice -> out.
// Tile 128 wide x 32 rows; smem [3][48][128] staged via float4 (reflect in y).
// Thread = one x column, 16 rows (in 4 groups of 4). 256 threads.
// ---------------------------------------------------------------------------
__global__ __launch_bounds__(256, 2)
void vslice_kernel(const float* __restrict__ mid, const float* __restrict__ bg,
                   const float* __restrict__ gw1, const float* __restrict__ gb1,
                   const float* __restrict__ gw2, const float* __restrict__ gb2,
                   float* __restrict__ out)
{
    extern __shared__ float sm[];
    float* sMid = sm;            // 3*48*128 = 18432
    float* sW   = sm + 18432;    // 81

    const int tid = threadIdx.x;
    const int x0 = blockIdx.x * 128;
    const int y0 = blockIdx.y * 32;
    const int b  = blockIdx.z;

    if (tid < 81)
        sW[tid] = (tid < 48) ? gw1[tid]
                : (tid < 64) ? gb1[tid - 48]
                : (tid < 80) ? gw2[tid - 64] : gb2[0];

    // Stage 3 channels x 48 rows x 128 cols (rows y0-8 .. y0+39, reflect).
    for (int i = tid; i < 4608; i += 256) {
        int ch = i / 1536; int rem = i - ch*1536;
        int rr = rem >> 5; int c4 = rem & 31;
        int gy = reflect1024(y0 - 8 + rr);
        float4 v = __ldg((const float4*)(mid + (((long)(b*3 + ch))*1024 + gy)*1024 + x0) + c4);
        *((float4*)&sMid[(ch*48 + rr)*128] + c4) = v;
    }
    __syncthreads();

    const int x    = tid & 127;
    const int half = tid >> 7;       // 0: rows 0-15, 1: rows 16-31
    const int rbase = half*16;

    // x-dependent slice coords (fixed per thread)
    const int gx = x0 + x;
    const float gxv = (gx + 0.5f) * (1.0f/1024.0f) * 2.0f - 0.5f;
    const float xs  = fminf(fmaxf(((gxv + 1.0f)*16.0f - 1.0f)*0.5f, 0.0f), 15.0f);
    const float x0f = floorf(xs);
    const int   xi0 = (int)x0f;
    const float fx  = xs - x0f;
    const int   xi1 = min(xi0 + 1, 15);
    const float* bgb = bg + b*2048;

    #pragma unroll 1
    for (int g = 0; g < 4; g++) {
        const int rg = rbase + g*4;       // tile-row of first window start
        // load col windows: 20 rows per channel
        float c0[20], c1[20], c2[20];
        {
            const float* p0 = &sMid[(0*48 + rg)*128 + x];
            const float* p1 = &sMid[(1*48 + rg)*128 + x];
            const float* p2 = &sMid[(2*48 + rg)*128 + x];
            #pragma unroll
            for (int k = 0; k < 20; k++) {
                c0[k] = p0[k*128];
                c1[k] = p1[k*128];
                c2[k] = p2[k*128];
            }
        }
        // vertical blur for 4 outputs
        float vb0[4], vb1[4], vb2[4];
        #pragma unroll
        for (int d = 0; d < 4; d++) {
            float a0 = 0.0f, a1 = 0.0f, a2 = 0.0f;
            #pragma unroll
            for (int k = 0; k < 17; k++) {
                a0 = fmaf(GW[k], c0[d + k], a0);
                a1 = fmaf(GW[k], c1[d + k], a1);
                a2 = fmaf(GW[k], c2[d + k], a2);
            }
            vb0[d] = a0; vb1[d] = a1; vb2[d] = a2;
        }
        // head + sigmoid + slice + store for 4 rows
        #pragma unroll
        for (int d = 0; d < 4; d++) {
            float ssum = sW[80];
            #pragma unroll
            for (int o = 0; o < 16; o++) {
                float h = fmaf(sW[o*3], vb0[d],
                          fmaf(sW[o*3+1], vb1[d],
                          fmaf(sW[o*3+2], vb2[d], sW[48+o])));
                h = relu_(h);
                ssum = fmaf(sW[64+o], h, ssum);
            }
            float sig = 1.0f / (1.0f + __expf(-ssum));
            float guide = 2.0f*sig - 0.5f;

            int gy = y0 + rbase + g*4 + d;
            float gyv = (gy + 0.5f) * (1.0f/1024.0f) * 2.0f - 0.5f;
            float ys  = fminf(fmaxf(((gyv + 1.0f)*16.0f - 1.0f)*0.5f, 0.0f), 15.0f);
            float y0f = floorf(ys);
            int   yi0 = (int)y0f;
            float fy  = ys - y0f;
            int   yi1 = min(yi0 + 1, 15);

            float zs  = fminf(fmaxf(((guide + 1.0f)*8.0f - 1.0f)*0.5f, 0.0f), 7.0f);
            float z0f = floorf(zs);
            int   zi0 = (int)z0f;
            float fz  = zs - z0f;
            int   zi1 = min(zi0 + 1, 7);

            float v000 = __ldg(&bgb[zi0*256 + yi0*16 + xi0]);
            float v001 = __ldg(&bgb[zi0*256 + yi0*16 + xi1]);
            float v010 = __ldg(&bgb[zi0*256 + yi1*16 + xi0]);
            float v011 = __ldg(&bgb[zi0*256 + yi1*16 + xi1]);
            float v100 = __ldg(&bgb[zi1*256 + yi0*16 + xi0]);
            float v101 = __ldg(&bgb[zi1*256 + yi0*16 + xi1]);
            float v110 = __ldg(&bgb[zi1*256 + yi1*16 + xi0]);
            float v111 = __ldg(&bgb[zi1*256 + yi1*16 + xi1]);

            float cc00 = v000 + (v001 - v000)*fx;
            float cc01 = v010 + (v011 - v010)*fx;
            float cc10 = v100 + (v101 - v100)*fx;
            float cc11 = v110 + (v111 - v110)*fx;
            float cc0  = cc00 + (cc01 - cc00)*fy;
            float cc1  = cc10 + (cc11 - cc10)*fy;
            out[(long)b*1048576 + gy*1024 + gx] = cc0 + (cc1 - cc0)*fz;
        }
    }
}

// ---------------------------------------------------------------------------
// kernel_launch
// ---------------------------------------------------------------------------
extern "C" void kernel_launch(void* const* d_in, const int* in_sizes, int n_in,
                              void* d_out, int out_size)
{
    const float* lqs = (const float*)d_in[0];
    const float* evs = (const float*)d_in[1];
    const float* gw1 = (const float*)d_in[2];
    const float* gb1 = (const float*)d_in[3];
    const float* gw2 = (const float*)d_in[4];
    const float* gb2 = (const float*)d_in[5];
    const float* sw0 = (const float*)d_in[6];
    const float* sb0 = (const float*)d_in[7];
    const float* sw1 = (const float*)d_in[8];
    const float* sb1 = (const float*)d_in[9];
    const float* sw2 = (const float*)d_in[10];
    const float* sb2 = (const float*)d_in[11];
    const float* sw3 = (const float*)d_in[12];
    const float* sb3 = (const float*)d_in[13];
    const float* cw0 = (const float*)d_in[14];
    const float* cb0 = (const float*)d_in[15];
    const float* cw1 = (const float*)d_in[16];
    const float* cb1 = (const float*)d_in[17];
    const float* fw1 = (const float*)d_in[18];
    const float* fb1 = (const float*)d_in[19];
    const float* fw2 = (const float*)d_in[20];
    const float* fb2 = (const float*)d_in[21];
    const float* fw3 = (const float*)d_in[22];
    const float* fb3 = (const float*)d_in[23];
    const float* lw1 = (const float*)d_in[24];
    const float* lb1 = (const float*)d_in[25];
    const float* lw2 = (const float*)d_in[26];
    const float* fuw = (const float*)d_in[27];
    const float* fub = (const float*)d_in[28];
    float* out = (float*)d_out;

    float *ps0, *ps1, *ps2, *ps3, *pl1, *pxl, *pc0, *pxg, *pbg, *pmid;
    cudaGetSymbolAddress((void**)&ps0, g_s0);
    cudaGetSymbolAddress((void**)&ps1, g_s1);
    cudaGetSymbolAddress((void**)&ps2, g_s2);
    cudaGetSymbolAddress((void**)&ps3, g_s3);
    cudaGetSymbolAddress((void**)&pl1, g_l1);
    cudaGetSymbolAddress((void**)&pxl, g_xl);
    cudaGetSymbolAddress((void**)&pc0, g_c0);
    cudaGetSymbolAddress((void**)&pxg, g_xg);
    cudaGetSymbolAddress((void**)&pbg, g_bg);
    cudaGetSymbolAddress((void**)&pmid, g_mid);

    // Dynamic smem sizes (bytes)
    const int SM_S0  = (18*33*33 + 8*18*9)  * 4;   //  83592
    const int SM_S1  = (8*33*33  + 16*8*9)  * 4;   //  39456
    const int SM_S2  = (16*33*33 + 16*16*9) * 4;   //  78912
    const int SM_S3  = (32*33*33 + 16*32*9) * 4;   // 157824
    const int SM_LW  = (64*18*19 + 8*64*9)  * 4;   // 105984
    const int SM_CW0 = (64*17*17 + 32*64*9) * 4;   // 147712
    const int SM_FC  = (7040 + 36864 + 1024 + 256 + 128) * 4;  // 181248
    const int SM_VS  = (18432 + 81) * 4;           //  74052

    static cudaStream_t s_side = nullptr, s_cw = nullptr;
    static cudaEvent_t  ev_fork = nullptr, ev_hb = nullptr, ev_s3 = nullptr, ev_cw = nullptr;
    if (!s_side) {
        cudaStreamCreateWithFlags(&s_side, cudaStreamNonBlocking);
        cudaStreamCreateWithFlags(&s_cw,   cudaStreamNonBlocking);
        cudaEventCreateWithFlags(&ev_fork, cudaEventDisableTiming);
        cudaEventCreateWithFlags(&ev_hb,   cudaEventDisableTiming);
        cudaEventCreateWithFlags(&ev_s3,   cudaEventDisableTiming);
        cudaEventCreateWithFlags(&ev_cw,   cudaEventDisableTiming);
        cudaFuncSetAttribute(s0f_kernel, cudaFuncAttributeMaxDynamicSharedMemorySize, SM_S0);
        cudaFuncSetAttribute(convf3_kernel<16,2,16,2,16,8,2,true,true>,  cudaFuncAttributeMaxDynamicSharedMemorySize, SM_S2);
        cudaFuncSetAttribute(convf3_kernel<32,2,16,2,16,8,2,true,true>,  cudaFuncAttributeMaxDynamicSharedMemorySize, SM_S3);
        cudaFuncSetAttribute(convf3_kernel<64,1,8,1,16,8,2,true,true>,   cudaFuncAttributeMaxDynamicSharedMemorySize, SM_LW);
        cudaFuncSetAttribute(convf3_kernel<64,1,8,1,16,8,2,false,false>, cudaFuncAttributeMaxDynamicSharedMemorySize, SM_LW);
        cudaFuncSetAttribute(convf3_kernel<64,2,32,1,8,8,1,true,true>,   cudaFuncAttributeMaxDynamicSharedMemorySize, SM_CW0);
        cudaFuncSetAttribute(cw1fc_kernel, cudaFuncAttributeMaxDynamicSharedMemorySize, SM_FC);
        cudaFuncSetAttribute(vslice_kernel, cudaFuncAttributeMaxDynamicSharedMemorySize, SM_VS);
    }

    // ---- fork: h-blur runs concurrent with the lowres chain ----
    cudaEventRecord(ev_fork, 0);
    cudaStreamWaitEvent(s_side, ev_fork, 0);
    hblur_kernel<<<dim3(256, 3, 8), 256, 0, s_side>>>(lqs, pmid);

    // ---- lowres trunk (R12-proven convf3 chain) ----
    s0f_kernel<<<dim3(64, 1, 8), 256, SM_S0>>>(lqs, evs, sw0, sb0, ps0);
    convf3_kernel<8,2,16,2,16,8,2,true,true>
        <<<dim3(16, 1, 8), 256, SM_S1>>>(ps0, sw1, sb1, ps1, 128, 128, 16, 64, 64, 4);
    convf3_kernel<16,2,16,2,16,8,2,true,true>
        <<<dim3(4, 2, 8), 256, SM_S2>>>(ps1, sw2, sb2, ps2, 64, 64, 32, 32, 32, 2);
    convf3_kernel<32,2,16,2,16,8,2,true,true>
        <<<dim3(1, 4, 8), 256, SM_S3>>>(ps2, sw3, sb3, ps3, 32, 32, 64, 16, 16, 1);

    // ---- fork global head (cw0 -> cw1fc) onto s_cw, local head on main ----
    cudaEventRecord(ev_s3, 0);
    cudaStreamWaitEvent(s_cw, ev_s3, 0);
    convf3_kernel<64,2,32,1,8,8,1,true,true>
        <<<dim3(1, 2, 8), 256, SM_CW0, s_cw>>>(ps3, cw0, cb0, pc0, 16, 16, 64, 8, 8, 1);
    cw1fc_kernel<<<8, 256, SM_FC, s_cw>>>(pc0, cw1, cb1, fw1, fb1, fw2, fb2, fw3, fb3, pxg);
    cudaEventRecord(ev_cw, s_cw);

    convf3_kernel<64,1,8,1,16,8,2,true,true>
        <<<dim3(1, 8, 8), 256, SM_LW>>>(ps3, lw1, lb1, pl1, 16, 16, 64, 16, 16, 1);
    convf3_kernel<64,1,8,1,16,8,2,false,false>
        <<<dim3(1, 8, 8), 256, SM_LW>>>(pl1, lw2, (const float*)nullptr, pxl, 16, 16, 64, 16, 16, 1);

    // ---- join heads, build bilateral grid ----
    cudaStreamWaitEvent(0, ev_cw, 0);
    bg_kernel<<<8, 256>>>(pxl, pxg, fuw, fub, pbg);

    // ---- join h-blur; fused v-blur + head + slice ----
    cudaEventRecord(ev_hb, s_side);
    cudaStreamWaitEvent(0, ev_hb, 0);
    vslice_kernel<<<dim3(8, 32, 8), 256, SM_VS>>>(pmid, pbg, gw1, gb1, gw2, gb2, out);
}

// round 16
// speedup vs baseline: 1.4470x; 1.0429x over previous
#include <cuda_runtime.h>

// ---------------------------------------------------------------------------
// Scratch (no allocation allowed -> __device__ globals)
// ---------------------------------------------------------------------------
static __device__ float g_s0[8*8*128*128];    // conv s0 out [8,8,128,128]
static __device__ float g_s1[8*16*64*64];     // [8,16,64,64]
static __device__ float g_s2[8*32*32*32];     // [8,32,32,32]
static __device__ float g_s3[8*64*16*16];     // [8,64,16,16]
static __device__ float g_l1[8*64*16*16];     // lw1 out
static __device__ float g_xl[8*64*16*16];     // lw2 out (local head)
static __device__ float g_c0[8*64*8*8];       // cw0 out
static __device__ float g_xg[8*64];           // fc3 out
static __device__ float g_bg[8*8*16*16];      // bilateral grid [B,8,16,16]
static __device__ float g_mid[8*3*1024*1024]; // h-blurred lqs
static __device__ float g_guide[8*1024*1024]; // guide map [B,1024,1024]

__device__ __forceinline__ float relu_(float x){ return fmaxf(x, 0.0f); }

__device__ __forceinline__ float warp_sum(float v){
    #pragma unroll
    for (int o = 16; o > 0; o >>= 1) v += __shfl_down_sync(0xffffffffu, v, o);
    return v;
}

// Gaussian(sigma=2), 17 taps, normalized. Compile-time literals -> FFMA-imm.
static __device__ constexpr float GW[17] = {
    6.691630e-05f, 4.363500e-04f, 2.215960e-03f, 8.764310e-03f,
    2.699596e-02f, 6.475993e-02f, 1.209875e-01f, 1.760357e-01f,
    1.994747e-01f,
    1.760357e-01f, 1.209875e-01f, 6.475993e-02f, 2.699596e-02f,
    8.764310e-03f, 2.215960e-03f, 4.363500e-04f, 6.691630e-05f
};

__device__ __forceinline__ int reflect1024(int i) {
    return i < 0 ? -i : (i > 1023 ? 2046 - i : i);
}

// ---------------------------------------------------------------------------
// convf3: 3x3 conv (pad=1, stride S). Whole input staged once per block with
// register-batched loads (8 LDG in flight -> 8 STS), 256 threads, one sync.
// ---------------------------------------------------------------------------
template<int CIN, int S, int COB, int CPT, int TY, int TX, int XG, bool RELU, bool HB>
__global__ void convf3_kernel(const float* __restrict__ in, const float* __restrict__ wt,
                              const float* __restrict__ bias, float* __restrict__ out,
                              int HIN, int WIN, int Cout, int HOUT, int WOUT, int tilesX)
{
    constexpr int TILEW = TX*XG;
    constexpr int PH  = (TY-1)*S + 3;
    constexpr int PW  = (TILEW-1)*S + 3;
    constexpr int PWP = (PW % 2 == 0) ? PW + 1 : PW;
    constexpr int CG  = COB/CPT;
    constexpr int NT  = CG*TY*XG;
    constexpr int WR  = (TX-1)*S + 3;
    constexpr int TOT = CIN*PH*PW;
    constexpr int WTOT = COB*CIN*9;
    constexpr int NB  = (TOT + NT*8 - 1)/(NT*8);

    extern __shared__ float sm[];
    float* sIn = sm;
    float* sW  = sm + CIN*PH*PWP;

    const int b     = blockIdx.z;
    const int co0   = blockIdx.y * COB;
    const int tileX = (blockIdx.x % tilesX) * TILEW;
    const int tileY = (blockIdx.x / tilesX) * TY;
    const int tid   = threadIdx.x;

    const int iy0 = tileY*S - 1, ix0 = tileX*S - 1;
    const float* inb = in + (long)b*CIN*HIN*WIN;

    #pragma unroll 1
    for (int bb = 0; bb < NB; bb++) {
        float v[8];
        #pragma unroll
        for (int j = 0; j < 8; j++) {
            int i = (bb*8 + j)*NT + tid;
            v[j] = 0.0f;
            if (i < TOT) {
                int ci = i / (PH*PW); int rem = i - ci*(PH*PW);
                int r = rem / PW;     int c = rem - r*PW;
                int iy = iy0 + r, ix = ix0 + c;
                if ((unsigned)iy < (unsigned)HIN && (unsigned)ix < (unsigned)WIN)
                    v[j] = __ldg(&inb[(ci*HIN + iy)*WIN + ix]);
            }
        }
        #pragma unroll
        for (int j = 0; j < 8; j++) {
            int i = (bb*8 + j)*NT + tid;
            if (i < TOT) {
                int ci = i / (PH*PW); int rem = i - ci*(PH*PW);
                int r = rem / PW;     int c = rem - r*PW;
                sIn[(ci*PH + r)*PWP + c] = v[j];
            }
        }
    }
    for (int i = tid; i < WTOT; i += NT)
        sW[i] = __ldg(&wt[(long)co0*CIN*9 + i]);
    __syncthreads();

    const int y  = tid % TY;
    const int cg = (tid / TY) % CG;
    const int xg = tid / (TY*CG);

    float acc[CPT][TX];
    #pragma unroll
    for (int c = 0; c < CPT; c++)
        #pragma unroll
        for (int x = 0; x < TX; x++) acc[c][x] = 0.0f;

    #pragma unroll 1
    for (int ci = 0; ci < CIN; ci++) {
        float w[CPT][9];
        #pragma unroll
        for (int c = 0; c < CPT; c++)
            #pragma unroll
            for (int k = 0; k < 9; k++)
                w[c][k] = sW[(cg*CPT + c)*CIN*9 + ci*9 + k];
        #pragma unroll
        for (int ky = 0; ky < 3; ky++) {
            const float* rp = &sIn[(ci*PH + y*S + ky)*PWP + xg*TX*S];
            float row[WR];
            #pragma unroll
            for (int j = 0; j < WR; j++) row[j] = rp[j];
            #pragma unroll
            for (int x = 0; x < TX; x++)
                #pragma unroll
                for (int kx = 0; kx < 3; kx++)
                    #pragma unroll
                    for (int c = 0; c < CPT; c++)
                        acc[c][x] = fmaf(row[x*S + kx], w[c][ky*3 + kx], acc[c][x]);
        }
    }

    #pragma unroll
    for (int c = 0; c < CPT; c++) {
        int co = co0 + cg*CPT + c;
        float bv = HB ? bias[co] : 0.0f;
        #pragma unroll
        for (int x = 0; x < TX; x++) {
            float v = acc[c][x] + bv;
            if (RELU) v = relu_(v);
            out[((b*Cout + co)*HOUT + tileY + y)*WOUT + tileX + xg*TX + x] = v;
        }
    }
}

// ---------------------------------------------------------------------------
// s0: in = concat(nearest(lqs,256), evs) [8,18,256,256] -> conv3x3 s2 p1 relu
// ---------------------------------------------------------------------------
__global__ void s0f_kernel(const float* __restrict__ lqs, const float* __restrict__ evs,
                           const float* __restrict__ wt,  const float* __restrict__ bias,
                           float* __restrict__ out)
{
    constexpr int PH = 33, PW = 33, PWP = 33, NT = 256;
    constexpr int TOT = 18*PH*PW;
    constexpr int NB  = (TOT + NT*16 - 1)/(NT*16);
    extern __shared__ float sm[];
    float* sIn = sm;
    float* sW  = sm + 18*PH*PWP;

    const int b     = blockIdx.z;
    const int tileX = (blockIdx.x % 8) * 16;
    const int tileY = (blockIdx.x / 8) * 16;
    const int tid   = threadIdx.x;

    const int iy0 = tileY*2 - 1, ix0 = tileX*2 - 1;

    #pragma unroll 1
    for (int bb = 0; bb < NB; bb++) {
        float v[16];
        #pragma unroll
        for (int j = 0; j < 16; j++) {
            int i = (bb*16 + j)*NT + tid;
            v[j] = 0.0f;
            if (i < TOT) {
                int ci = i / (PH*PW); int rem = i - ci*(PH*PW);
                int r = rem / PW;     int c = rem - r*PW;
                int iy = iy0 + r, ix = ix0 + c;
                if ((unsigned)iy < 256u && (unsigned)ix < 256u) {
                    if (ci < 3) v[j] = __ldg(&lqs[(b*3 + ci)*1048576 + iy*4096 + ix*4]);
                    else        v[j] = __ldg(&evs[(b*15 + (ci-3))*65536 + iy*256 + ix]);
                }
            }
        }
        #pragma unroll
        for (int j = 0; j < 16; j++) {
            int i = (bb*16 + j)*NT + tid;
            if (i < TOT) {
                int ci = i / (PH*PW); int rem = i - ci*(PH*PW);
                int r = rem / PW;     int c = rem - r*PW;
                sIn[(ci*PH + r)*PWP + c] = v[j];
            }
        }
    }
    for (int i = tid; i < 8*18*9; i += NT) sW[i] = __ldg(&wt[i]);
    __syncthreads();

    const int y  = tid % 16;
    const int cg = (tid / 16) % 8;
    const int xg = tid / 128;

    float acc[8];
    #pragma unroll
    for (int x = 0; x < 8; x++) acc[x] = 0.0f;

    #pragma unroll 1
    for (int ci = 0; ci < 18; ci++) {
        float w[9];
        #pragma unroll
        for (int k = 0; k < 9; k++) w[k] = sW[(cg*18 + ci)*9 + k];
        #pragma unroll
        for (int ky = 0; ky < 3; ky++) {
            const float* rp = &sIn[(ci*PH + y*2 + ky)*PWP + xg*16];
            float row[17];
            #pragma unroll
            for (int j = 0; j < 17; j++) row[j] = rp[j];
            #pragma unroll
            for (int x = 0; x < 8; x++)
                #pragma unroll
                for (int kx = 0; kx < 3; kx++)
                    acc[x] = fmaf(row[x*2 + kx], w[ky*3 + kx], acc[x]);
        }
    }

    float bv = bias[cg];
    #pragma unroll
    for (int x = 0; x < 8; x++)
        out[((b*8 + cg)*128 + tileY + y)*128 + tileX + xg*8 + x] = relu_(acc[x] + bv);
}

// ---------------------------------------------------------------------------
// Fused cw1 (conv3x3 s2: [64,8,8]->[64,4,4]) + FC 1024->256->128->64.
// ---------------------------------------------------------------------------
__global__ void cw1fc_kernel(const float* __restrict__ c0,
                             const float* __restrict__ cw1, const float* __restrict__ cb1,
                             const float* __restrict__ fw1, const float* __restrict__ fb1,
                             const float* __restrict__ fw2, const float* __restrict__ fb2,
                             const float* __restrict__ fw3, const float* __restrict__ fb3,
                             float* __restrict__ xg)
{
    extern __shared__ float sm[];
    float* sC  = sm;             // 7040
    float* sWt = sC + 7040;      // 36864
    float* sc1 = sWt + 36864;    // 1024
    float* s1f = sc1 + 1024;     // 256
    float* s2f = s1f + 256;      // 128

    const int b = blockIdx.x, tid = threadIdx.x;

    for (int i = tid; i < 64*10*10; i += 256) {
        int ci = i / 100; int rem = i - ci*100;
        int r = rem / 10, c = rem - (rem/10)*10;
        int iy = r - 1, ix = c - 1;
        float v = 0.0f;
        if ((unsigned)iy < 8u && (unsigned)ix < 8u)
            v = c0[((b*64 + ci)*8 + iy)*8 + ix];
        sC[(ci*10 + r)*11 + c] = v;
    }
    for (int i = tid; i < 36864; i += 256) sWt[i] = cw1[i];
    __syncthreads();

    {
        int co = tid >> 2, y = tid & 3;
        float acc[4] = {0.0f, 0.0f, 0.0f, 0.0f};
        #pragma unroll 1
        for (int ci = 0; ci < 64; ci++) {
            float w[9];
            #pragma unroll
            for (int k = 0; k < 9; k++) w[k] = sWt[(co*64 + ci)*9 + k];
            #pragma unroll
            for (int ky = 0; ky < 3; ky++) {
                const float* rp = &sC[(ci*10 + y*2 + ky)*11];
                float row[9];
                #pragma unroll
                for (int j = 0; j < 9; j++) row[j] = rp[j];
                #pragma unroll
                for (int x = 0; x < 4; x++)
                    #pragma unroll
                    for (int kx = 0; kx < 3; kx++)
                        acc[x] = fmaf(row[x*2 + kx], w[ky*3 + kx], acc[x]);
            }
        }
        float bv = cb1[co];
        #pragma unroll
        for (int x = 0; x < 4; x++)
            sc1[co*16 + y*4 + x] = relu_(acc[x] + bv);
    }
    __syncthreads();

    const int lane = tid & 31, wp = tid >> 5;

    for (int j0 = 0; j0 < 32; j0 += 4) {
        int o = wp*32 + j0;
        const float* w0 = fw1 + o*1024;
        float a0 = 0.0f, a1 = 0.0f, a2 = 0.0f, a3 = 0.0f;
        #pragma unroll 4
        for (int k = lane; k < 1024; k += 32) {
            float xv = sc1[k];
            a0 = fmaf(w0[k],        xv, a0);
            a1 = fmaf(w0[k + 1024], xv, a1);
            a2 = fmaf(w0[k + 2048], xv, a2);
            a3 = fmaf(w0[k + 3072], xv, a3);
        }
        a0 = warp_sum(a0); a1 = warp_sum(a1); a2 = warp_sum(a2); a3 = warp_sum(a3);
        if (lane == 0) {
            s1f[o]   = relu_(a0 + fb1[o]);
            s1f[o+1] = relu_(a1 + fb1[o+1]);
            s1f[o+2] = relu_(a2 + fb1[o+2]);
            s1f[o+3] = relu_(a3 + fb1[o+3]);
        }
    }
    __syncthreads();

    for (int j0 = 0; j0 < 16; j0 += 4) {
        int o = wp*16 + j0;
        const float* w0 = fw2 + o*256;
        float a0 = 0.0f, a1 = 0.0f, a2 = 0.0f, a3 = 0.0f;
        #pragma unroll
        for (int k = lane; k < 256; k += 32) {
            float xv = s1f[k];
            a0 = fmaf(w0[k],       xv, a0);
            a1 = fmaf(w0[k + 256], xv, a1);
            a2 = fmaf(w0[k + 512], xv, a2);
            a3 = fmaf(w0[k + 768], xv, a3);
        }
        a0 = warp_sum(a0); a1 = warp_sum(a1); a2 = warp_sum(a2); a3 = warp_sum(a3);
        if (lane == 0) {
            s2f[o]   = relu_(a0 + fb2[o]);
            s2f[o+1] = relu_(a1 + fb2[o+1]);
            s2f[o+2] = relu_(a2 + fb2[o+2]);
            s2f[o+3] = relu_(a3 + fb2[o+3]);
        }
    }
    __syncthreads();

    for (int j0 = 0; j0 < 8; j0 += 4) {
        int o = wp*8 + j0;
        const float* w0 = fw3 + o*128;
        float a0 = 0.0f, a1 = 0.0f, a2 = 0.0f, a3 = 0.0f;
        #pragma unroll
        for (int k = lane; k < 128; k += 32) {
            float xv = s2f[k];
            a0 = fmaf(w0[k],       xv, a0);
            a1 = fmaf(w0[k + 128], xv, a1);
            a2 = fmaf(w0[k + 256], xv, a2);
            a3 = fmaf(w0[k + 384], xv, a3);
        }
        a0 = warp_sum(a0); a1 = warp_sum(a1); a2 = warp_sum(a2); a3 = warp_sum(a3);
        if (lane == 0) {
            xg[b*64 + o]   = a0 + fb3[o];
            xg[b*64 + o+1] = a1 + fb3[o+1];
            xg[b*64 + o+2] = a2 + fb3[o+2];
            xg[b*64 + o+3] = a3 + fb3[o+3];
        }
    }
}

// ---------------------------------------------------------------------------
// bg = conv1x1(relu(xg[b,c] + xl[b,c,y,x]), fuw) + fub  -> [B,8,16,16]
// ---------------------------------------------------------------------------
__global__ void bg_kernel(const float* __restrict__ xl, const float* __restrict__ xg,
                          const float* __restrict__ fuw, const float* __restrict__ fub,
                          float* __restrict__ bg)
{
    int b = blockIdx.x, p = threadIdx.x;
    __shared__ float sxg[64];
    __shared__ float sw[8*64];
    if (p < 64) sxg[p] = xg[b*64 + p];
    for (int i = p; i < 512; i += 256) sw[i] = fuw[i];
    __syncthreads();
    float acc[8];
    #pragma unroll
    for (int g = 0; g < 8; g++) acc[g] = fub[g];
    for (int c = 0; c < 64; c++) {
        float f = relu_(sxg[c] + xl[(b*64 + c)*256 + p]);
        #pragma unroll
        for (int g = 0; g < 8; g++) acc[g] = fmaf(sw[g*64 + c], f, acc[g]);
    }
    #pragma unroll
    for (int g = 0; g < 8; g++) bg[(b*8 + g)*256 + p] = acc[g];
}

// ---------------------------------------------------------------------------
// hblur_kernel: horizontal 17-tap Gaussian, reflect pad, global->global.
// ---------------------------------------------------------------------------
__global__ __launch_bounds__(256)
void hblur_kernel(const float* __restrict__ lqs, float* __restrict__ mid)
{
    const int tid = threadIdx.x;
    const int t = tid & 63;
    const int r = tid >> 6;
    const int ch = blockIdx.y, b = blockIdx.z;
    const int y = blockIdx.x*4 + r;
    const float* row  = lqs + ((b*3 + ch)*1024 + y)*1024;
    float*       orow = mid + ((b*3 + ch)*1024 + y)*1024;
    const int x0 = t*16;

    float w[48];
    if (t == 0 || t == 63) {
        #pragma unroll
        for (int j = 0; j < 48; j++) w[j] = __ldg(&row[reflect1024(x0 - 8 + j)]);
    } else {
        const float4* p = (const float4*)(row + x0 - 8);
        #pragma unroll
        for (int j = 0; j < 12; j++) {
            float4 v = __ldg(&p[j]);
            w[j*4] = v.x; w[j*4+1] = v.y; w[j*4+2] = v.z; w[j*4+3] = v.w;
        }
    }

    #pragma unroll
    for (int o = 0; o < 16; o += 4) {
        float a0 = 0.0f, a1 = 0.0f, a2 = 0.0f, a3 = 0.0f;
        #pragma unroll
        for (int k = 0; k < 17; k++) {
            a0 = fmaf(GW[k], w[o + k],     a0);
            a1 = fmaf(GW[k], w[o + 1 + k], a1);
            a2 = fmaf(GW[k], w[o + 2 + k], a2);
            a3 = fmaf(GW[k], w[o + 3 + k], a3);
        }
        *(float4*)(orow + x0 + o) = make_float4(a0, a1, a2, a3);
    }
}

// ---------------------------------------------------------------------------
// vguide_kernel: vertical blur + 1x1 head + sigmoid -> guide map.
// Tile 128 wide x 32 rows; smem [3][48][128]. No bg dependency -> overlappable.
// ---------------------------------------------------------------------------
__global__ __launch_bounds__(256, 2)
void vguide_kernel(const float* __restrict__ mid,
                   const float* __restrict__ gw1, const float* __restrict__ gb1,
                   const float* __restrict__ gw2, const float* __restrict__ gb2,
                   float* __restrict__ guide)
{
    extern __shared__ float sm[];
    float* sMid = sm;            // 3*48*128 = 18432
    float* sW   = sm + 18432;    // 81

    const int tid = threadIdx.x;
    const int x0 = blockIdx.x * 128;
    const int y0 = blockIdx.y * 32;
    const int b  = blockIdx.z;

    if (tid < 81)
        sW[tid] = (tid < 48) ? gw1[tid]
                : (tid < 64) ? gb1[tid - 48]
                : (tid < 80) ? gw2[tid - 64] : gb2[0];

    for (int i = tid; i < 4608; i += 256) {
        int ch = i / 1536; int rem = i - ch*1536;
        int rr = rem >> 5; int c4 = rem & 31;
        int gy = reflect1024(y0 - 8 + rr);
        float4 v = __ldg((const float4*)(mid + (((long)(b*3 + ch))*1024 + gy)*1024 + x0) + c4);
        *((float4*)&sMid[(ch*48 + rr)*128] + c4) = v;
    }
    __syncthreads();

    const int x    = tid & 127;
    const int half = tid >> 7;
    const int rbase = half*16;
    const int gx = x0 + x;

    #pragma unroll 1
    for (int g = 0; g < 4; g++) {
        const int rg = rbase + g*4;
        float c0[20], c1[20], c2[20];
        {
            const float* p0 = &sMid[(0*48 + rg)*128 + x];
            const float* p1 = &sMid[(1*48 + rg)*128 + x];
            const float* p2 = &sMid[(2*48 + rg)*128 + x];
            #pragma unroll
            for (int k = 0; k < 20; k++) {
                c0[k] = p0[k*128];
                c1[k] = p1[k*128];
                c2[k] = p2[k*128];
            }
        }
        #pragma unroll
        for (int d = 0; d < 4; d++) {
            float a0 = 0.0f, a1 = 0.0f, a2 = 0.0f;
            #pragma unroll
            for (int k = 0; k < 17; k++) {
                a0 = fmaf(GW[k], c0[d + k], a0);
                a1 = fmaf(GW[k], c1[d + k], a1);
                a2 = fmaf(GW[k], c2[d + k], a2);
            }
            float ssum = sW[80];
            #pragma unroll
            for (int o = 0; o < 16; o++) {
                float h = fmaf(sW[o*3], a0, fmaf(sW[o*3+1], a1, fmaf(sW[o*3+2], a2, sW[48+o])));
                h = relu_(h);
                ssum = fmaf(sW[64+o], h, ssum);
            }
            float sig = 1.0f / (1.0f + __expf(-ssum));
            int gy = y0 + rbase + g*4 + d;
            guide[(long)b*1048576 + gy*1024 + gx] = 2.0f*sig - 0.5f;
        }
    }
}

// ---------------------------------------------------------------------------
// slice_kernel: trilinear slice of bilateral grid using guide map. float4 I/O.
// ---------------------------------------------------------------------------
__global__ void slice_kernel(const float* __restrict__ guide,
                             const float* __restrict__ bg, float* __restrict__ out)
{
    int idx = blockIdx.x*256 + threadIdx.x;
    int b   = idx >> 18;
    int rem = idx & 0x3FFFF;
    int py  = rem >> 8;
    int px0 = (rem & 255) << 2;

    float4 g4 = ((const float4*)guide)[idx];
    float gv[4] = {g4.x, g4.y, g4.z, g4.w};

    float gyv = (py + 0.5f) * (1.0f/1024.0f) * 2.0f - 0.5f;
    float ys  = fminf(fmaxf(((gyv + 1.0f)*16.0f - 1.0f)*0.5f, 0.0f), 15.0f);
    float y0f = floorf(ys);
    int   y0  = (int)y0f;
    float fy  = ys - y0f;
    int   y1  = min(y0 + 1, 15);

    const float* bgb = bg + b*2048;
    float res[4];
    #pragma unroll
    for (int j = 0; j < 4; j++) {
        int px = px0 + j;
        float gxv = (px + 0.5f) * (1.0f/1024.0f) * 2.0f - 0.5f;
        float xs  = fminf(fmaxf(((gxv + 1.0f)*16.0f - 1.0f)*0.5f, 0.0f), 15.0f);
        float x0f = floorf(xs);
        int   x0  = (int)x0f;
        float fx  = xs - x0f;
        int   x1  = min(x0 + 1, 15);

        float zs  = fminf(fmaxf(((gv[j] + 1.0f)*8.0f - 1.0f)*0.5f, 0.0f), 7.0f);
        float z0f = floorf(zs);
        int   z0  = (int)z0f;
        float fz  = zs - z0f;
        int   z1  = min(z0 + 1, 7);

        float v000 = __ldg(&bgb[z0*256 + y0*16 + x0]);
        float v001 = __ldg(&bgb[z0*256 + y0*16 + x1]);
        float v010 = __ldg(&bgb[z0*256 + y1*16 + x0]);
        float v011 = __ldg(&bgb[z0*256 + y1*16 + x1]);
        float v100 = __ldg(&bgb[z1*256 + y0*16 + x0]);
        float v101 = __ldg(&bgb[z1*256 + y0*16 + x1]);
        float v110 = __ldg(&bgb[z1*256 + y1*16 + x0]);
        float v111 = __ldg(&bgb[z1*256 + y1*16 + x1]);

        float c00 = v000 + (v001 - v000)*fx;
        float c01 = v010 + (v011 - v010)*fx;
        float c10 = v100 + (v101 - v100)*fx;
        float c11 = v110 + (v111 - v110)*fx;
        float c0v = c00 + (c01 - c00)*fy;
        float c1v = c10 + (c11 - c10)*fy;
        res[j] = c0v + (c1v - c0v)*fz;
    }
    ((float4*)out)[idx] = make_float4(res[0], res[1], res[2], res[3]);
}

// ---------------------------------------------------------------------------
// kernel_launch
// ---------------------------------------------------------------------------
extern "C" void kernel_launch(void* const* d_in, const int* in_sizes, int n_in,
                              void* d_out, int out_size)
{
    const float* lqs = (const float*)d_in[0];
    const float* evs = (const float*)d_in[1];
    const float* gw1 = (const float*)d_in[2];
    const float* gb1 = (const float*)d_in[3];
    const float* gw2 = (const float*)d_in[4];
    const float* gb2 = (const float*)d_in[5];
    const float* sw0 = (const float*)d_in[6];
    const float* sb0 = (const float*)d_in[7];
    const float* sw1 = (const float*)d_in[8];
    const float* sb1 = (const float*)d_in[9];
    const float* sw2 = (const float*)d_in[10];
    const float* sb2 = (const float*)d_in[11];
    const float* sw3 = (const float*)d_in[12];
    const float* sb3 = (const float*)d_in[13];
    const float* cw0 = (const float*)d_in[14];
    const float* cb0 = (const float*)d_in[15];
    const float* cw1 = (const float*)d_in[16];
    const float* cb1 = (const float*)d_in[17];
    const float* fw1 = (const float*)d_in[18];
    const float* fb1 = (const float*)d_in[19];
    const float* fw2 = (const float*)d_in[20];
    const float* fb2 = (const float*)d_in[21];
    const float* fw3 = (const float*)d_in[22];
    const float* fb3 = (const float*)d_in[23];
    const float* lw1 = (const float*)d_in[24];
    const float* lb1 = (const float*)d_in[25];
    const float* lw2 = (const float*)d_in[26];
    const float* fuw = (const float*)d_in[27];
    const float* fub = (const float*)d_in[28];
    float* out = (float*)d_out;

    float *ps0, *ps1, *ps2, *ps3, *pl1, *pxl, *pc0, *pxg, *pbg, *pmid, *pgd;
    cudaGetSymbolAddress((void**)&ps0, g_s0);
    cudaGetSymbolAddress((void**)&ps1, g_s1);
    cudaGetSymbolAddress((void**)&ps2, g_s2);
    cudaGetSymbolAddress((void**)&ps3, g_s3);
    cudaGetSymbolAddress((void**)&pl1, g_l1);
    cudaGetSymbolAddress((void**)&pxl, g_xl);
    cudaGetSymbolAddress((void**)&pc0, g_c0);
    cudaGetSymbolAddress((void**)&pxg, g_xg);
    cudaGetSymbolAddress((void**)&pbg, g_bg);
    cudaGetSymbolAddress((void**)&pmid, g_mid);
    cudaGetSymbolAddress((void**)&pgd, g_guide);

    // Dynamic smem sizes (bytes)
    const int SM_S0  = (18*33*33 + 8*18*9)  * 4;   //  83592
    const int SM_S1  = (8*33*33  + 8*8*9)   * 4;   //  37152
    const int SM_S2  = (16*33*33 + 8*16*9)  * 4;   //  74304
    const int SM_S3  = (32*17*33 + 8*32*9)  * 4;   //  81024
    const int SM_LW  = (64*10*19 + 8*64*9)  * 4;   //  67072
    const int SM_CW0 = (64*17*17 + 32*64*9) * 4;   // 147712
    const int SM_FC  = (7040 + 36864 + 1024 + 256 + 128) * 4;  // 181248
    const int SM_VG  = (18432 + 81) * 4;           //  74052

    static cudaStream_t s_side = nullptr, s_cw = nullptr;
    static cudaEvent_t  ev_fork = nullptr, ev_gd = nullptr, ev_s3 = nullptr, ev_cw = nullptr;
    if (!s_side) {
        cudaStreamCreateWithFlags(&s_side, cudaStreamNonBlocking);
        cudaStreamCreateWithFlags(&s_cw,   cudaStreamNonBlocking);
        cudaEventCreateWithFlags(&ev_fork, cudaEventDisableTiming);
        cudaEventCreateWithFlags(&ev_gd,   cudaEventDisableTiming);
        cudaEventCreateWithFlags(&ev_s3,   cudaEventDisableTiming);
        cudaEventCreateWithFlags(&ev_cw,   cudaEventDisableTiming);
        cudaFuncSetAttribute(s0f_kernel, cudaFuncAttributeMaxDynamicSharedMemorySize, SM_S0);
        cudaFuncSetAttribute(convf3_kernel<16,2,8,1,16,8,2,true,true>,   cudaFuncAttributeMaxDynamicSharedMemorySize, SM_S2);
        cudaFuncSetAttribute(convf3_kernel<32,2,8,1,8,4,4,true,true>,    cudaFuncAttributeMaxDynamicSharedMemorySize, SM_S3);
        cudaFuncSetAttribute(convf3_kernel<64,1,8,1,8,4,4,true,true>,    cudaFuncAttributeMaxDynamicSharedMemorySize, SM_LW);
        cudaFuncSetAttribute(convf3_kernel<64,1,8,1,8,4,4,false,false>,  cudaFuncAttributeMaxDynamicSharedMemorySize, SM_LW);
        cudaFuncSetAttribute(convf3_kernel<64,2,32,1,8,8,1,true,true>,   cudaFuncAttributeMaxDynamicSharedMemorySize, SM_CW0);
        cudaFuncSetAttribute(cw1fc_kernel, cudaFuncAttributeMaxDynamicSharedMemorySize, SM_FC);
        cudaFuncSetAttribute(vguide_kernel, cudaFuncAttributeMaxDynamicSharedMemorySize, SM_VG);
    }

    // ---- fork: hblur -> vguide run concurrent with the lowres trunk ----
    cudaEventRecord(ev_fork, 0);
    cudaStreamWaitEvent(s_side, ev_fork, 0);
    hblur_kernel<<<dim3(256, 3, 8), 256, 0, s_side>>>(lqs, pmid);
    vguide_kernel<<<dim3(8, 32, 8), 256, SM_VG, s_side>>>(pmid, gw1, gb1, gw2, gb2, pgd);
    cudaEventRecord(ev_gd, s_side);

    // ---- lowres trunk (re-gridded convf3 chain) ----
    s0f_kernel<<<dim3(64, 1, 8), 256, SM_S0>>>(lqs, evs, sw0, sb0, ps0);
    convf3_kernel<8,2,8,1,16,8,2,true,true>
        <<<dim3(16, 2, 8), 256, SM_S1>>>(ps0, sw1, sb1, ps1, 128, 128, 16, 64, 64, 4);
    convf3_kernel<16,2,8,1,16,8,2,true,true>
        <<<dim3(4, 4, 8), 256, SM_S2>>>(ps1, sw2, sb2, ps2, 64, 64, 32, 32, 32, 2);
    convf3_kernel<32,2,8,1,8,4,4,true,true>
        <<<dim3(2, 8, 8), 256, SM_S3>>>(ps2, sw3, sb3, ps3, 32, 32, 64, 16, 16, 1);

    // ---- fork global head (cw0 -> cw1fc) onto s_cw, local head on main ----
    cudaEventRecord(ev_s3, 0);
    cudaStreamWaitEvent(s_cw, ev_s3, 0);
    convf3_kernel<64,2,32,1,8,8,1,true,true>
        <<<dim3(1, 2, 8), 256, SM_CW0, s_cw>>>(ps3, cw0, cb0, pc0, 16, 16, 64, 8, 8, 1);
    cw1fc_kernel<<<8, 256, SM_FC, s_cw>>>(pc0, cw1, cb1, fw1, fb1, fw2, fb2, fw3, fb3, pxg);
    cudaEventRecord(ev_cw, s_cw);

    convf3_kernel<64,1,8,1,8,4,4,true,true>
        <<<dim3(2, 8, 8), 256, SM_LW>>>(ps3, lw1, lb1, pl1, 16, 16, 64, 16, 16, 1);
    convf3_kernel<64,1,8,1,8,4,4,false,false>
        <<<dim3(2, 8, 8), 256, SM_LW>>>(pl1, lw2, (const float*)nullptr, pxl, 16, 16, 64, 16, 16, 1);

    // ---- join heads, build bilateral grid ----
    cudaStreamWaitEvent(0, ev_cw, 0);
    bg_kernel<<<8, 256>>>(pxl, pxg, fuw, fub, pbg);

    // ---- join guide; slice ----
    cudaStreamWaitEvent(0, ev_gd, 0);
    slice_kernel<<<8192, 256>>>(pgd, pbg, out);
}